// round 2
// baseline (speedup 1.0000x reference)
#include <cuda_runtime.h>

#define NN 100000
#define NE 1600000

// ---------------- scratch (static device allocations only) ----------------
__device__ float g_T[NN * 128];    // (X @ W) * norm_out, current layer
__device__ float g_H1[NN * 128];   // layer-1 activation (kept for residual)
__device__ float g_H2[NN * 128];   // layer-2 activation
__device__ float g_norm_out[NN];
__device__ float g_norm_in[NN];
__device__ int   g_deg_out[NN];
__device__ int   g_deg_in[NN];
__device__ int   g_rowptr[NN + 1];
__device__ int   g_fill[NN];
__device__ int   g_col[NE];
__device__ int   g_is64;           // 1 if src/dst are int64, 0 if int32

// ---------------- index dtype detection ----------------
// Values are uniform in [0, 100000). If the buffer were int32, the odds that
// 64 consecutive odd words are all zero are astronomically small. If it is
// int64 (little-endian), every odd word is the high half == 0.
__global__ void detect_kernel(const int* __restrict__ src_raw) {
    if (threadIdx.x == 0 && blockIdx.x == 0) {
        int is64 = 1;
        for (int i = 0; i < 64; ++i)
            if (src_raw[2 * i + 1] != 0) { is64 = 0; break; }
        g_is64 = is64;
    }
}

__device__ __forceinline__ int load_idx(const void* p, int e, int is64) {
    if (is64) return (int)((const long long*)p)[e];
    return ((const int*)p)[e];
}

// ---------------- graph preprocessing ----------------
__global__ void init_kernel() {
    int i = blockIdx.x * blockDim.x + threadIdx.x;
    if (i < NN) { g_deg_out[i] = 0; g_deg_in[i] = 0; g_fill[i] = 0; }
}

__global__ void count_kernel(const void* __restrict__ src,
                             const void* __restrict__ dst) {
    int e = blockIdx.x * blockDim.x + threadIdx.x;
    int is64 = g_is64;
    if (e < NE) {
        atomicAdd(&g_deg_out[load_idx(src, e, is64)], 1);
        atomicAdd(&g_deg_in[load_idx(dst, e, is64)], 1);
    }
}

// exclusive prefix sum of g_deg_in -> g_rowptr, single block of 1024
__global__ void scan_kernel() {
    __shared__ int sh[1024];
    int tid = threadIdx.x;
    int carry = 0;
    for (int base = 0; base < NN; base += 1024) {
        int i = base + tid;
        int v = (i < NN) ? g_deg_in[i] : 0;
        sh[tid] = v;
        __syncthreads();
        #pragma unroll
        for (int off = 1; off < 1024; off <<= 1) {
            int t = (tid >= off) ? sh[tid - off] : 0;
            __syncthreads();
            sh[tid] += t;
            __syncthreads();
        }
        if (i < NN) g_rowptr[i] = carry + sh[tid] - v;
        int total = sh[1023];
        carry += total;
        __syncthreads();
    }
    if (tid == 0) g_rowptr[NN] = carry;
}

__global__ void norm_kernel() {
    int i = blockIdx.x * blockDim.x + threadIdx.x;
    if (i < NN) {
        g_norm_out[i] = rsqrtf((float)max(g_deg_out[i], 1));
        g_norm_in[i]  = rsqrtf((float)max(g_deg_in[i], 1));
    }
}

__global__ void fill_kernel(const void* __restrict__ src,
                            const void* __restrict__ dst) {
    int e = blockIdx.x * blockDim.x + threadIdx.x;
    int is64 = g_is64;
    if (e < NE) {
        int d = load_idx(dst, e, is64);
        int p = g_rowptr[d] + atomicAdd(&g_fill[d], 1);
        g_col[p] = load_idx(src, e, is64);
    }
}

// ---------------- GEMM: g_T = (A @ W) * norm_out[:,None] ----------------
// A is [NN,128] row-major, W is [128,BN] row-major.
// SRCSEL: 0 = external pointer Xext, 1 = g_H1, 2 = 0.9*g_H1 + 0.1*g_H2
template <int BN, int SRCSEL>
__global__ __launch_bounds__(256) void gemm_kernel(const float* __restrict__ Xext,
                                                   const float* __restrict__ W) {
    constexpr int BM = 128, BK = 16, TM = 8, TN = BN / 16;
    __shared__ float Xs[BK][BM];
    __shared__ float Ws[BK][BN];

    const int tid = threadIdx.x;
    const int tx = tid & 15;
    const int ty = tid >> 4;
    const int m0 = blockIdx.x * BM;

    float acc[TM][TN];
    #pragma unroll
    for (int i = 0; i < TM; ++i)
        #pragma unroll
        for (int j = 0; j < TN; ++j) acc[i][j] = 0.f;

    for (int kc = 0; kc < 128; kc += BK) {
        // --- load A tile (transposed into Xs[k][m]) ---
        #pragma unroll
        for (int l = 0; l < (BM * BK) / 1024; ++l) {
            int lin = tid + l * 256;          // float4 index
            int row = lin >> 2;               // BK/4 = 4 float4 per row
            int kq  = (lin & 3) << 2;
            int gr  = m0 + row;
            float4 v = make_float4(0.f, 0.f, 0.f, 0.f);
            if (gr < NN) {
                if (SRCSEL == 0) {
                    v = *(const float4*)(Xext + gr * 128 + kc + kq);
                } else if (SRCSEL == 1) {
                    v = *(const float4*)(g_H1 + gr * 128 + kc + kq);
                } else {
                    float4 a = *(const float4*)(g_H1 + gr * 128 + kc + kq);
                    float4 b = *(const float4*)(g_H2 + gr * 128 + kc + kq);
                    v = make_float4(0.9f * a.x + 0.1f * b.x,
                                    0.9f * a.y + 0.1f * b.y,
                                    0.9f * a.z + 0.1f * b.z,
                                    0.9f * a.w + 0.1f * b.w);
                }
            }
            Xs[kq + 0][row] = v.x;
            Xs[kq + 1][row] = v.y;
            Xs[kq + 2][row] = v.z;
            Xs[kq + 3][row] = v.w;
        }
        // --- load W tile ---
        #pragma unroll
        for (int l = 0; l < (BK * BN) / 1024; ++l) {
            int lin = tid + l * 256;
            int k = lin / (BN / 4);
            int nq = (lin % (BN / 4)) * 4;
            *(float4*)&Ws[k][nq] = *(const float4*)(W + (kc + k) * BN + nq);
        }
        __syncthreads();

        #pragma unroll
        for (int k = 0; k < BK; ++k) {
            float a[TM], b[TN];
            #pragma unroll
            for (int i = 0; i < TM; ++i) a[i] = Xs[k][ty * TM + i];
            #pragma unroll
            for (int j = 0; j < TN; ++j) b[j] = Ws[k][tx * TN + j];
            #pragma unroll
            for (int i = 0; i < TM; ++i)
                #pragma unroll
                for (int j = 0; j < TN; ++j) acc[i][j] += a[i] * b[j];
        }
        __syncthreads();
    }

    // epilogue: scale by norm_out and store to g_T (stride BN)
    #pragma unroll
    for (int i = 0; i < TM; ++i) {
        int m = m0 + ty * TM + i;
        if (m < NN) {
            float no = g_norm_out[m];
            #pragma unroll
            for (int j = 0; j < TN; j += 4) {
                float4 v = make_float4(acc[i][j + 0] * no, acc[i][j + 1] * no,
                                       acc[i][j + 2] * no, acc[i][j + 3] * no);
                *(float4*)&g_T[m * BN + tx * TN + j] = v;
            }
        }
    }
}

// ---------------- aggregation: out = (sum_{e in-edges} T[src]) * norm_in + b ----------------
// one warp per destination node; FEAT=128 -> float4/lane, FEAT=64 -> float2/lane
template <int FEAT, bool RELU, int OUTSEL>   // OUTSEL: 0=g_H1, 1=g_H2, 2=Oext
__global__ __launch_bounds__(256) void agg_kernel(const float* __restrict__ bias,
                                                  float* __restrict__ Oext) {
    int w = (blockIdx.x * 256 + threadIdx.x) >> 5;
    int lane = threadIdx.x & 31;
    if (w >= NN) return;
    int s0 = g_rowptr[w];
    int s1 = g_rowptr[w + 1];
    float ni = g_norm_in[w];

    if (FEAT == 128) {
        const int off = lane * 4;
        float4 a = make_float4(0.f, 0.f, 0.f, 0.f);
        int e = s0;
        for (; e + 4 <= s1; e += 4) {
            int c0 = g_col[e + 0], c1 = g_col[e + 1];
            int c2 = g_col[e + 2], c3 = g_col[e + 3];
            float4 t0 = *(const float4*)(g_T + c0 * 128 + off);
            float4 t1 = *(const float4*)(g_T + c1 * 128 + off);
            float4 t2 = *(const float4*)(g_T + c2 * 128 + off);
            float4 t3 = *(const float4*)(g_T + c3 * 128 + off);
            a.x += t0.x + t1.x + t2.x + t3.x;
            a.y += t0.y + t1.y + t2.y + t3.y;
            a.z += t0.z + t1.z + t2.z + t3.z;
            a.w += t0.w + t1.w + t2.w + t3.w;
        }
        for (; e < s1; ++e) {
            int c = g_col[e];
            float4 t = *(const float4*)(g_T + c * 128 + off);
            a.x += t.x; a.y += t.y; a.z += t.z; a.w += t.w;
        }
        float4 b = *(const float4*)(bias + off);
        float4 r = make_float4(fmaf(a.x, ni, b.x), fmaf(a.y, ni, b.y),
                               fmaf(a.z, ni, b.z), fmaf(a.w, ni, b.w));
        if (RELU) {
            r.x = fmaxf(r.x, 0.f); r.y = fmaxf(r.y, 0.f);
            r.z = fmaxf(r.z, 0.f); r.w = fmaxf(r.w, 0.f);
        }
        float* dstp = (OUTSEL == 0) ? g_H1 : (OUTSEL == 1) ? g_H2 : Oext;
        *(float4*)(dstp + w * 128 + off) = r;
    } else {
        const int off = lane * 2;
        float2 a = make_float2(0.f, 0.f);
        int e = s0;
        for (; e + 4 <= s1; e += 4) {
            int c0 = g_col[e + 0], c1 = g_col[e + 1];
            int c2 = g_col[e + 2], c3 = g_col[e + 3];
            float2 t0 = *(const float2*)(g_T + c0 * 64 + off);
            float2 t1 = *(const float2*)(g_T + c1 * 64 + off);
            float2 t2 = *(const float2*)(g_T + c2 * 64 + off);
            float2 t3 = *(const float2*)(g_T + c3 * 64 + off);
            a.x += t0.x + t1.x + t2.x + t3.x;
            a.y += t0.y + t1.y + t2.y + t3.y;
        }
        for (; e < s1; ++e) {
            int c = g_col[e];
            float2 t = *(const float2*)(g_T + c * 64 + off);
            a.x += t.x; a.y += t.y;
        }
        float2 b = *(const float2*)(bias + off);
        float2 r = make_float2(fmaf(a.x, ni, b.x), fmaf(a.y, ni, b.y));
        if (RELU) { r.x = fmaxf(r.x, 0.f); r.y = fmaxf(r.y, 0.f); }
        float* dstp = (OUTSEL == 0) ? g_H1 : (OUTSEL == 1) ? g_H2 : Oext;
        *(float2*)(dstp + w * 64 + off) = r;
    }
}

// ---------------- driver ----------------
extern "C" void kernel_launch(void* const* d_in, const int* in_sizes, int n_in,
                              void* d_out, int out_size) {
    const float* x   = (const float*)d_in[0];
    const void*  src = d_in[1];
    const void*  dst = d_in[2];
    const float* W1 = (const float*)d_in[3];
    const float* b1 = (const float*)d_in[4];
    const float* W2 = (const float*)d_in[5];
    const float* b2 = (const float*)d_in[6];
    const float* W3 = (const float*)d_in[7];
    const float* b3 = (const float*)d_in[8];
    float* out = (float*)d_out;

    const int NB_N = (NN + 255) / 256;
    const int NB_E = (NE + 255) / 256;
    const int NB_G = (NN + 127) / 128;          // 782 GEMM row tiles
    const int NB_A = (NN * 32 + 255) / 256;     // one warp per node

    // graph preprocessing (recomputed every launch; deterministic work)
    detect_kernel<<<1, 32>>>((const int*)src);
    init_kernel<<<NB_N, 256>>>();
    count_kernel<<<NB_E, 256>>>(src, dst);
    scan_kernel<<<1, 1024>>>();
    norm_kernel<<<NB_N, 256>>>();
    fill_kernel<<<NB_E, 256>>>(src, dst);

    // layer 1: h1 = relu(agg(x@W1 * no) * ni + b1)
    gemm_kernel<128, 0><<<NB_G, 256>>>(x, W1);
    agg_kernel<128, true, 0><<<NB_A, 256>>>(b1, nullptr);

    // layer 2: h2 = relu(agg(h1@W2 * no) * ni + b2)
    gemm_kernel<128, 1><<<NB_G, 256>>>(nullptr, W2);
    agg_kernel<128, true, 1><<<NB_A, 256>>>(b2, nullptr);

    // layer 3: out = agg((0.9*h1 + 0.1*h2)@W3 * no) * ni + b3
    gemm_kernel<64, 2><<<NB_G, 256>>>(nullptr, W3);
    agg_kernel<64, false, 2><<<NB_A, 256>>>(b3, out);
}

// round 3
// speedup vs baseline: 1.2829x; 1.2829x over previous
#include <cuda_runtime.h>

#define NN 100000
#define NE 1600000
#define SCAN_BLK ((NN + 1023) / 1024)   // 98

// ---------------- scratch (static device allocations only) ----------------
__device__ float g_T[NN * 128];    // (X @ W) * norm_out, current layer
__device__ float g_H1[NN * 128];   // layer-1 activation (kept for residual)
__device__ float g_H2[NN * 128];   // layer-2 activation
__device__ float g_norm_out[NN];
__device__ float g_norm_in[NN];
__device__ int   g_deg_out[NN];
__device__ int   g_deg_in[NN];
__device__ int   g_rowptr[NN + 1];
__device__ int   g_fill[NN];
__device__ int   g_col[NE];
__device__ int   g_bsum[SCAN_BLK];
__device__ int   g_is64;           // 1 if src/dst are int64, 0 if int32

// ---------------- index dtype detection ----------------
__global__ void detect_kernel(const int* __restrict__ src_raw) {
    if (threadIdx.x == 0 && blockIdx.x == 0) {
        int is64 = 1;
        for (int i = 0; i < 64; ++i)
            if (src_raw[2 * i + 1] != 0) { is64 = 0; break; }
        g_is64 = is64;
    }
}

__device__ __forceinline__ int load_idx(const void* p, int e, int is64) {
    if (is64) return (int)((const long long*)p)[e];
    return ((const int*)p)[e];
}

// ---------------- graph preprocessing ----------------
__global__ void init_kernel() {
    int i = blockIdx.x * blockDim.x + threadIdx.x;
    if (i < NN) { g_deg_out[i] = 0; g_deg_in[i] = 0; g_fill[i] = 0; }
}

__global__ void count_kernel(const void* __restrict__ src,
                             const void* __restrict__ dst) {
    int e = blockIdx.x * blockDim.x + threadIdx.x;
    int is64 = g_is64;
    if (e < NE) {
        atomicAdd(&g_deg_out[load_idx(src, e, is64)], 1);
        atomicAdd(&g_deg_in[load_idx(dst, e, is64)], 1);
    }
}

// -------- multi-block exclusive scan of g_deg_in -> g_rowptr --------
// Phase A: per-block warp-shuffle scan; per-block exclusive results + totals
__global__ __launch_bounds__(1024) void scanA_kernel() {
    __shared__ int wsum[32];
    int i = blockIdx.x * 1024 + threadIdx.x;
    int lane = threadIdx.x & 31, wid = threadIdx.x >> 5;
    int v = (i < NN) ? g_deg_in[i] : 0;
    int x = v;
    #pragma unroll
    for (int o = 1; o < 32; o <<= 1) {
        int t = __shfl_up_sync(0xffffffffu, x, o);
        if (lane >= o) x += t;
    }
    if (lane == 31) wsum[wid] = x;
    __syncthreads();
    if (wid == 0) {
        int y = wsum[lane];
        #pragma unroll
        for (int o = 1; o < 32; o <<= 1) {
            int t = __shfl_up_sync(0xffffffffu, y, o);
            if (lane >= o) y += t;
        }
        wsum[lane] = y;
    }
    __syncthreads();
    int excl = x - v + (wid > 0 ? wsum[wid - 1] : 0);
    if (i < NN) g_rowptr[i] = excl;
    if (threadIdx.x == 1023) g_bsum[blockIdx.x] = excl + v;
}

// Phase B: serial scan of 98 block totals (trivial)
__global__ void scanB_kernel() {
    if (threadIdx.x == 0) {
        int s = 0;
        for (int b = 0; b < SCAN_BLK; ++b) {
            int t = g_bsum[b];
            g_bsum[b] = s;
            s += t;
        }
        g_rowptr[NN] = s;
    }
}

// Phase C: add block offsets; fused norm computation
__global__ void scanC_norm_kernel() {
    int i = blockIdx.x * blockDim.x + threadIdx.x;
    if (i < NN) {
        g_rowptr[i] += g_bsum[i >> 10];
        g_norm_out[i] = rsqrtf((float)max(g_deg_out[i], 1));
        g_norm_in[i]  = rsqrtf((float)max(g_deg_in[i], 1));
    }
}

__global__ void fill_kernel(const void* __restrict__ src,
                            const void* __restrict__ dst) {
    int e = blockIdx.x * blockDim.x + threadIdx.x;
    int is64 = g_is64;
    if (e < NE) {
        int d = load_idx(dst, e, is64);
        int p = g_rowptr[d] + atomicAdd(&g_fill[d], 1);
        g_col[p] = load_idx(src, e, is64);
    }
}

// ---------------- GEMM: g_T = (A @ W) * norm_out[:,None] ----------------
// SRCSEL: 0 = external pointer Xext, 1 = g_H1, 2 = 0.9*g_H1 + 0.1*g_H2
template <int BN, int SRCSEL>
__global__ __launch_bounds__(256) void gemm_kernel(const float* __restrict__ Xext,
                                                   const float* __restrict__ W) {
    constexpr int BM = 128, BK = 16, TM = 8, TN = BN / 16;
    __shared__ float Xs[BK][BM];
    __shared__ float Ws[BK][BN];

    const int tid = threadIdx.x;
    const int tx = tid & 15;
    const int ty = tid >> 4;
    const int m0 = blockIdx.x * BM;

    float acc[TM][TN];
    #pragma unroll
    for (int i = 0; i < TM; ++i)
        #pragma unroll
        for (int j = 0; j < TN; ++j) acc[i][j] = 0.f;

    for (int kc = 0; kc < 128; kc += BK) {
        #pragma unroll
        for (int l = 0; l < (BM * BK) / 1024; ++l) {
            int lin = tid + l * 256;
            int row = lin >> 2;
            int kq  = (lin & 3) << 2;
            int gr  = m0 + row;
            float4 v = make_float4(0.f, 0.f, 0.f, 0.f);
            if (gr < NN) {
                if (SRCSEL == 0) {
                    v = *(const float4*)(Xext + gr * 128 + kc + kq);
                } else if (SRCSEL == 1) {
                    v = *(const float4*)(g_H1 + gr * 128 + kc + kq);
                } else {
                    float4 a = *(const float4*)(g_H1 + gr * 128 + kc + kq);
                    float4 b = *(const float4*)(g_H2 + gr * 128 + kc + kq);
                    v = make_float4(0.9f * a.x + 0.1f * b.x,
                                    0.9f * a.y + 0.1f * b.y,
                                    0.9f * a.z + 0.1f * b.z,
                                    0.9f * a.w + 0.1f * b.w);
                }
            }
            Xs[kq + 0][row] = v.x;
            Xs[kq + 1][row] = v.y;
            Xs[kq + 2][row] = v.z;
            Xs[kq + 3][row] = v.w;
        }
        #pragma unroll
        for (int l = 0; l < (BK * BN) / 1024; ++l) {
            int lin = tid + l * 256;
            int k = lin / (BN / 4);
            int nq = (lin % (BN / 4)) * 4;
            *(float4*)&Ws[k][nq] = *(const float4*)(W + (kc + k) * BN + nq);
        }
        __syncthreads();

        #pragma unroll
        for (int k = 0; k < BK; ++k) {
            float a[TM], b[TN];
            #pragma unroll
            for (int i = 0; i < TM; ++i) a[i] = Xs[k][ty * TM + i];
            #pragma unroll
            for (int j = 0; j < TN; ++j) b[j] = Ws[k][tx * TN + j];
            #pragma unroll
            for (int i = 0; i < TM; ++i)
                #pragma unroll
                for (int j = 0; j < TN; ++j) acc[i][j] += a[i] * b[j];
        }
        __syncthreads();
    }

    #pragma unroll
    for (int i = 0; i < TM; ++i) {
        int m = m0 + ty * TM + i;
        if (m < NN) {
            float no = g_norm_out[m];
            #pragma unroll
            for (int j = 0; j < TN; j += 4) {
                float4 v = make_float4(acc[i][j + 0] * no, acc[i][j + 1] * no,
                                       acc[i][j + 2] * no, acc[i][j + 3] * no);
                *(float4*)&g_T[m * BN + tx * TN + j] = v;
            }
        }
    }
}

// ---------------- aggregation ----------------
template <int FEAT, bool RELU, int OUTSEL>   // OUTSEL: 0=g_H1, 1=g_H2, 2=Oext
__global__ __launch_bounds__(256) void agg_kernel(const float* __restrict__ bias,
                                                  float* __restrict__ Oext) {
    int w = (blockIdx.x * 256 + threadIdx.x) >> 5;
    int lane = threadIdx.x & 31;
    if (w >= NN) return;
    int s0 = g_rowptr[w];
    int s1 = g_rowptr[w + 1];
    float ni = g_norm_in[w];

    if (FEAT == 128) {
        const int off = lane * 4;
        float4 a = make_float4(0.f, 0.f, 0.f, 0.f);
        int e = s0;
        for (; e + 4 <= s1; e += 4) {
            int c0 = g_col[e + 0], c1 = g_col[e + 1];
            int c2 = g_col[e + 2], c3 = g_col[e + 3];
            float4 t0 = *(const float4*)(g_T + c0 * 128 + off);
            float4 t1 = *(const float4*)(g_T + c1 * 128 + off);
            float4 t2 = *(const float4*)(g_T + c2 * 128 + off);
            float4 t3 = *(const float4*)(g_T + c3 * 128 + off);
            a.x += t0.x + t1.x + t2.x + t3.x;
            a.y += t0.y + t1.y + t2.y + t3.y;
            a.z += t0.z + t1.z + t2.z + t3.z;
            a.w += t0.w + t1.w + t2.w + t3.w;
        }
        for (; e < s1; ++e) {
            int c = g_col[e];
            float4 t = *(const float4*)(g_T + c * 128 + off);
            a.x += t.x; a.y += t.y; a.z += t.z; a.w += t.w;
        }
        float4 b = *(const float4*)(bias + off);
        float4 r = make_float4(fmaf(a.x, ni, b.x), fmaf(a.y, ni, b.y),
                               fmaf(a.z, ni, b.z), fmaf(a.w, ni, b.w));
        if (RELU) {
            r.x = fmaxf(r.x, 0.f); r.y = fmaxf(r.y, 0.f);
            r.z = fmaxf(r.z, 0.f); r.w = fmaxf(r.w, 0.f);
        }
        float* dstp = (OUTSEL == 0) ? g_H1 : (OUTSEL == 1) ? g_H2 : Oext;
        *(float4*)(dstp + w * 128 + off) = r;
    } else {
        const int off = lane * 2;
        float2 a = make_float2(0.f, 0.f);
        int e = s0;
        for (; e + 4 <= s1; e += 4) {
            int c0 = g_col[e + 0], c1 = g_col[e + 1];
            int c2 = g_col[e + 2], c3 = g_col[e + 3];
            float2 t0 = *(const float2*)(g_T + c0 * 64 + off);
            float2 t1 = *(const float2*)(g_T + c1 * 64 + off);
            float2 t2 = *(const float2*)(g_T + c2 * 64 + off);
            float2 t3 = *(const float2*)(g_T + c3 * 64 + off);
            a.x += t0.x + t1.x + t2.x + t3.x;
            a.y += t0.y + t1.y + t2.y + t3.y;
        }
        for (; e < s1; ++e) {
            int c = g_col[e];
            float2 t = *(const float2*)(g_T + c * 64 + off);
            a.x += t.x; a.y += t.y;
        }
        float2 b = *(const float2*)(bias + off);
        float2 r = make_float2(fmaf(a.x, ni, b.x), fmaf(a.y, ni, b.y));
        if (RELU) { r.x = fmaxf(r.x, 0.f); r.y = fmaxf(r.y, 0.f); }
        float* dstp = (OUTSEL == 0) ? g_H1 : (OUTSEL == 1) ? g_H2 : Oext;
        *(float2*)(dstp + w * 64 + off) = r;
    }
}

// ---------------- driver ----------------
extern "C" void kernel_launch(void* const* d_in, const int* in_sizes, int n_in,
                              void* d_out, int out_size) {
    const float* x   = (const float*)d_in[0];
    const void*  src = d_in[1];
    const void*  dst = d_in[2];
    const float* W1 = (const float*)d_in[3];
    const float* b1 = (const float*)d_in[4];
    const float* W2 = (const float*)d_in[5];
    const float* b2 = (const float*)d_in[6];
    const float* W3 = (const float*)d_in[7];
    const float* b3 = (const float*)d_in[8];
    float* out = (float*)d_out;

    const int NB_N = (NN + 255) / 256;
    const int NB_E = (NE + 255) / 256;
    const int NB_G = (NN + 127) / 128;
    const int NB_A = (NN * 32 + 255) / 256;

    // graph preprocessing
    detect_kernel<<<1, 32>>>((const int*)src);
    init_kernel<<<NB_N, 256>>>();
    count_kernel<<<NB_E, 256>>>(src, dst);
    scanA_kernel<<<SCAN_BLK, 1024>>>();
    scanB_kernel<<<1, 32>>>();
    scanC_norm_kernel<<<NB_N, 256>>>();
    fill_kernel<<<NB_E, 256>>>(src, dst);

    // layer 1
    gemm_kernel<128, 0><<<NB_G, 256>>>(x, W1);
    agg_kernel<128, true, 0><<<NB_A, 256>>>(b1, nullptr);

    // layer 2
    gemm_kernel<128, 1><<<NB_G, 256>>>(nullptr, W2);
    agg_kernel<128, true, 1><<<NB_A, 256>>>(b2, nullptr);

    // layer 3
    gemm_kernel<64, 2><<<NB_G, 256>>>(nullptr, W3);
    agg_kernel<64, false, 2><<<NB_A, 256>>>(b3, out);
}